// round 7
// baseline (speedup 1.0000x reference)
#include <cuda_runtime.h>
#include <cstdint>
#include <math.h>

#define TOKENS 16384
#define KDIM   2048
#define NEXP   64
#define TM     64                       // tokens per CTA
#define KC     64                       // K elems per chunk
#define NCHUNK (KDIM / KC)              // 32
#define SA_X   272                      // x fp32 row stride bytes (16B-mult, spread banks)
#define X_STAGE (64 * SA_X)             // 17408
#define SA_B   144                      // W bf16 row stride bytes (conflict-free ldmatrix)
#define OFF_BH X_STAGE
#define OFF_BL (X_STAGE + 64 * SA_B)
#define STAGE  (X_STAGE + 2 * 64 * SA_B)  // 35840
#define NSTAGE 3
#define DYN_SMEM (NSTAGE * STAGE)         // 107520 -> 2 CTAs/SM
#define RESCUE_TH 3e-4f

typedef unsigned int u32;

// Pre-split W planes (bf16 pairs packed in u32), refreshed every call.
__device__ __align__(16) u32 g_Whi[NEXP * KDIM / 2];
__device__ __align__(16) u32 g_Wlo[NEXP * KDIM / 2];

// ---------------- helpers ----------------
static __device__ __forceinline__ u32 smem_u32(const void* p) {
    u32 a;
    asm("{ .reg .u64 t; cvta.to.shared.u64 t, %1; cvt.u32.u64 %0, t; }" : "=r"(a) : "l"(p));
    return a;
}
static __device__ __forceinline__ u32 cvt_bf2(float f0, float f1) {
    u32 r;
    asm("cvt.rn.bf16x2.f32 %0, %1, %2;" : "=r"(r) : "f"(f1), "f"(f0));
    return r;
}
static __device__ __forceinline__ float2 lds64(u32 a) {
    float2 v;
    asm volatile("ld.shared.v2.f32 {%0,%1}, [%2];" : "=f"(v.x), "=f"(v.y) : "r"(a));
    return v;
}
static __device__ __forceinline__ u32 prmt7632(u32 a, u32 b) {
    u32 d;
    asm("prmt.b32 %0, %1, %2, 0x7632;" : "=r"(d) : "r"(a), "r"(b));
    return d;
}
static __device__ __forceinline__ void cpasync16(u32 dst, const void* src) {
    asm volatile("cp.async.cg.shared.global [%0], [%1], 16;" :: "r"(dst), "l"(src) : "memory");
}
#define CP_COMMIT() asm volatile("cp.async.commit_group;" ::: "memory")
#define CP_WAIT0()  asm volatile("cp.async.wait_group 0;" ::: "memory")
#define CP_WAIT1()  asm volatile("cp.async.wait_group 1;" ::: "memory")
static __device__ __forceinline__ void ldm_x4(u32* r, u32 a) {
    asm volatile("ldmatrix.sync.aligned.m8n8.x4.shared.b16 {%0,%1,%2,%3}, [%4];"
                 : "=r"(r[0]), "=r"(r[1]), "=r"(r[2]), "=r"(r[3]) : "r"(a));
}
static __device__ __forceinline__ void mma_bf16(float* c, const u32* a, const u32* b) {
    asm volatile("mma.sync.aligned.m16n8k16.row.col.f32.bf16.bf16.f32 "
                 "{%0,%1,%2,%3}, {%4,%5,%6,%7}, {%8,%9}, {%0,%1,%2,%3};"
                 : "+f"(c[0]), "+f"(c[1]), "+f"(c[2]), "+f"(c[3])
                 : "r"(a[0]), "r"(a[1]), "r"(a[2]), "r"(a[3]), "r"(b[0]), "r"(b[1]));
}

// Build Ah (truncation-split hi) + Al (exact-residual lo) from fp32 smem pair.
#define BUILD_A(ah, al, addr)                                                       \
    {                                                                               \
        float2 _v = lds64(addr);                                                    \
        u32 _b0 = __float_as_uint(_v.x), _b1 = __float_as_uint(_v.y);               \
        (ah) = prmt7632(_b0, _b1);                                                  \
        float _h0 = __uint_as_float(_b0 & 0xffff0000u);                             \
        float _h1 = __uint_as_float(_b1 & 0xffff0000u);                             \
        (al) = cvt_bf2(_v.x - _h0, _v.y - _h1);                                     \
    }

// ---------------- W pre-split kernel ----------------
__global__ void prep_w(const float* __restrict__ W) {
    int p = blockIdx.x * blockDim.x + threadIdx.x;   // pair index, 65536 total
    float2 xy = ((const float2*)W)[p];
    u32 h = cvt_bf2(xy.x, xy.y);
    float h0 = __uint_as_float(h << 16);
    float h1 = __uint_as_float(h & 0xffff0000u);
    u32 l = cvt_bf2(xy.x - h0, xy.y - h1);
    g_Whi[p] = h;
    g_Wlo[p] = l;
}

// ---------------- exact fp32 rescoring ----------------
__device__ __noinline__ float exact_dot(const float* __restrict__ xr, const float* __restrict__ wr) {
    float a0 = 0.f, a1 = 0.f, a2 = 0.f, a3 = 0.f;
    for (int k = 0; k < KDIM; k += 4) {
        a0 = fmaf(__ldg(xr + k + 0), __ldg(wr + k + 0), a0);
        a1 = fmaf(__ldg(xr + k + 1), __ldg(wr + k + 1), a1);
        a2 = fmaf(__ldg(xr + k + 2), __ldg(wr + k + 2), a2);
        a3 = fmaf(__ldg(xr + k + 3), __ldg(wr + k + 3), a3);
    }
    return (a0 + a1) + (a2 + a3);
}

// ---------------- main kernel ----------------
__global__ __launch_bounds__(256, 2)
void router_mma(const float* __restrict__ x,
                const float* __restrict__ W,
                const float* __restrict__ bias,
                float* __restrict__ out)
{
    extern __shared__ __align__(16) char dsmp[];
    const u32 sb = smem_u32(dsmp);
    __shared__ float s_bias[NEXP];

    const int tid  = threadIdx.x;
    const int wid  = tid >> 5;
    const int lane = tid & 31;
    const int wm   = wid & 1;          // M block (32 tokens)
    const int wn   = wid >> 1;         // N block (16 experts)
    const int tokBase = blockIdx.x * TM;

    if (tid < NEXP) s_bias[tid] = bias[tid];

    float acc[2][2][4];                // [mt m16][nt n8][frag]
#pragma unroll
    for (int i = 0; i < 2; i++)
#pragma unroll
        for (int j = 0; j < 2; j++)
#pragma unroll
            for (int q = 0; q < 4; q++) acc[i][j][q] = 0.f;

    const uint4* whp = (const uint4*)g_Whi;
    const uint4* wlp = (const uint4*)g_Wlo;

    // cp.async mapping: x 4 slots/thread, B 2 slots/thread/plane
    const int xrow = tid >> 4, xc16 = tid & 15;     // slot s=tid+256r: row s>>4, col s&15
    const int brow = tid >> 3, bc16 = tid & 7;

#define ISSUE_CHUNK(c, st)                                                          \
    {                                                                               \
        const u32 stb = sb + (st) * STAGE;                                          \
        _Pragma("unroll")                                                           \
        for (int r = 0; r < 4; r++) {                                               \
            int row = xrow + r * 16;                                                \
            cpasync16(stb + (u32)(row * SA_X + xc16 * 16),                          \
                      x + (size_t)(tokBase + row) * KDIM + (c) * KC + xc16 * 4);    \
        }                                                                           \
        _Pragma("unroll")                                                           \
        for (int r = 0; r < 2; r++) {                                               \
            int row = brow + r * 32;                                                \
            u32 d = stb + OFF_BH + (u32)(row * SA_B + bc16 * 16);                   \
            int idx = row * (KDIM / 8) + (c) * 8 + bc16;                            \
            cpasync16(d, whp + idx);                                                \
            cpasync16(d + (OFF_BL - OFF_BH), wlp + idx);                            \
        }                                                                           \
        CP_COMMIT();                                                                \
    }

    // consumer base offsets (stage-relative)
    const u32 aOff = (u32)((wm * 32 + (lane >> 2)) * SA_X + (lane & 3) * 8);
    const u32 bOff = (u32)(OFF_BH + (wn * 16 + ((lane >> 4) & 1) * 8 + (lane & 7)) * SA_B +
                           ((lane >> 3) & 1) * 16);

    // ---------------- prologue: fill 2 stages ----------------
    ISSUE_CHUNK(0, 0);
    ISSUE_CHUNK(1, 1);

    // ---------------- main loop ----------------
    int cur = 0;
    for (int c = 0; c < NCHUNK; c++) {
        if (c < NCHUNK - 1) { CP_WAIT1(); } else { CP_WAIT0(); }
        __syncthreads();                 // chunk c data visible; stage (c+2)%3 free

        if (c + 2 < NCHUNK) {
            int nst = cur + 2; if (nst >= NSTAGE) nst -= NSTAGE;
            ISSUE_CHUNK(c + 2, nst);
        }

        const u32 xs = sb + cur * STAGE;
        const u32 aBase = xs + aOff;
        const u32 bBase = xs + bOff;
#pragma unroll
        for (int ks = 0; ks < 4; ks++) {
            u32 Ah[2][4], Al[2][4], Bh[4], Bl[4];
            ldm_x4(Bh, bBase + ks * 32);
            ldm_x4(Bl, bBase + (OFF_BL - OFF_BH) + ks * 32);
#pragma unroll
            for (int mt = 0; mt < 2; mt++) {
                const u32 a0 = aBase + mt * (16 * SA_X) + ks * 64;
                BUILD_A(Ah[mt][0], Al[mt][0], a0);
                BUILD_A(Ah[mt][1], Al[mt][1], a0 + 8 * SA_X);
                BUILD_A(Ah[mt][2], Al[mt][2], a0 + 32);
                BUILD_A(Ah[mt][3], Al[mt][3], a0 + 8 * SA_X + 32);
            }
#pragma unroll
            for (int mt = 0; mt < 2; mt++)
#pragma unroll
                for (int nt = 0; nt < 2; nt++) {
                    mma_bf16(acc[mt][nt], Ah[mt], &Bh[nt * 2]);
                    mma_bf16(acc[mt][nt], Ah[mt], &Bl[nt * 2]);
                    mma_bf16(acc[mt][nt], Al[mt], &Bh[nt * 2]);
                }
        }
        cur++; if (cur >= NSTAGE) cur = 0;
    }

    // ---------------- epilogue ----------------
    __syncthreads();
    float* ls = (float*)dsmp;            // logits staging [64][65]
#pragma unroll
    for (int mt = 0; mt < 2; mt++)
#pragma unroll
        for (int nt = 0; nt < 2; nt++) {
            const int row = wm * 32 + mt * 16 + (lane >> 2);
            const int col = wn * 16 + nt * 8 + (lane & 3) * 2;
            ls[row * 65 + col]           = acc[mt][nt][0] + s_bias[col];
            ls[row * 65 + col + 1]       = acc[mt][nt][1] + s_bias[col + 1];
            ls[(row + 8) * 65 + col]     = acc[mt][nt][2] + s_bias[col];
            ls[(row + 8) * 65 + col + 1] = acc[mt][nt][3] + s_bias[col + 1];
        }
    __syncthreads();

    float* probs_out  = out;
    float* idx_out    = out + (size_t)TOKENS * 2;
    float* logits_out = out + (size_t)TOKENS * 4;

    // coalesced logits store: 1024 float4 per block, 4 per thread
#pragma unroll
    for (int r = 0; r < 4; r++) {
        int s  = tid + 256 * r;
        int t  = s >> 4;
        int e4 = s & 15;
        const float* lr = &ls[t * 65 + e4 * 4];
        *(float4*)(logits_out + (size_t)(tokBase + t) * NEXP + e4 * 4) =
            make_float4(lr[0], lr[1], lr[2], lr[3]);
    }

    // top-2 + softmax (+ exact rescue): one thread per token
    if (tid < TM) {
        const int t = tid;
        const int gt = tokBase + t;
        const float* lr = &ls[t * 65];
        float m1 = -INFINITY, m2 = -INFINITY, m3 = -INFINITY;
        int i1 = 0, i2 = 0;
#pragma unroll
        for (int e = 0; e < NEXP; e++) {
            const float v = lr[e];
            if (v > m1)      { m3 = m2; m2 = m1; i2 = i1; m1 = v; i1 = e; }
            else if (v > m2) { m3 = m2; m2 = v; i2 = e; }
            else if (v > m3) { m3 = v; }
        }
        float p1v = m1, p2v = m2;

        if ((m1 - m2 < RESCUE_TH) || (m2 - m3 < RESCUE_TH)) {
            const float thr = m2 - RESCUE_TH;
            float e1 = -INFINITY, e2 = -INFINITY;
            int j1 = 0, j2 = 0;
            const float* xr = x + (size_t)gt * KDIM;
#pragma unroll 1
            for (int e = 0; e < NEXP; e++) {
                if (lr[e] > thr) {
                    float ex = exact_dot(xr, W + (size_t)e * KDIM) + s_bias[e];
                    if (ex > e1)      { e2 = e1; j2 = j1; e1 = ex; j1 = e; }
                    else if (ex > e2) { e2 = ex; j2 = e; }
                }
            }
            i1 = j1; i2 = j2; p1v = e1; p2v = e2;
        }

        const float ex2 = expf(p2v - p1v);
        const float inv = 1.0f / (1.0f + ex2);
        probs_out[gt * 2 + 0] = inv;
        probs_out[gt * 2 + 1] = ex2 * inv;
        idx_out[gt * 2 + 0] = (float)i1;
        idx_out[gt * 2 + 1] = (float)i2;
    }
}

extern "C" void kernel_launch(void* const* d_in, const int* in_sizes, int n_in,
                              void* d_out, int out_size)
{
    const float* x = (const float*)d_in[0];
    const float* W = (const float*)d_in[1];
    const float* b = (const float*)d_in[2];
    float* out = (float*)d_out;

    cudaFuncSetAttribute(router_mma, cudaFuncAttributeMaxDynamicSharedMemorySize, DYN_SMEM);
    prep_w<<<256, 256>>>(W);
    router_mma<<<TOKENS / TM, 256, DYN_SMEM>>>(x, W, b, out);
}